// round 5
// baseline (speedup 1.0000x reference)
#include <cuda_runtime.h>
#include <cstdint>

// ============================================================================
// WaveletKAN: out[128,4096] = x @ W^T + wavelet(x) + bias
//   K1: wavelet (Haar DWT4 + rank-select quantile prune + IDWT) -> g_wav
//   K2: tf32 mma.sync GEMM, split-K=2 -> g_part[2]   (unchanged from R4)
//   K3: wide reduce: out = p0 + p1 + bias + g_wav
// ============================================================================

#define KDIM   4096
#define SK     2
#define KHALF  (KDIM / SK)        // 2048
#define BK     64
#define NT2    (KHALF / BK)       // 32
#define STAGES 3

__device__ float g_part[SK * 128 * 4096];   // split-K partials (4 MB)
__device__ float g_wav[128 * 4096];         // wavelet output (2 MB)

// ---------------------------------------------------------------------------
// GEMM helpers
// ---------------------------------------------------------------------------
__device__ __forceinline__ void cp_async16(uint32_t dst, const void* src) {
    asm volatile("cp.async.cg.shared.global [%0], [%1], 16;\n" :: "r"(dst), "l"(src));
}
__device__ __forceinline__ void ldsm_x4(uint32_t* d, uint32_t addr) {
    asm volatile("ldmatrix.sync.aligned.m8n8.x4.shared.b16 {%0,%1,%2,%3}, [%4];"
        : "=r"(d[0]), "=r"(d[1]), "=r"(d[2]), "=r"(d[3]) : "r"(addr));
}
__device__ __forceinline__ uint32_t f2tf(uint32_t v) {
    uint32_t r;
    asm("cvt.rna.tf32.f32 %0, %1;" : "=r"(r) : "f"(__uint_as_float(v)));
    return r;
}
__device__ __forceinline__ void mma_tf32(float* c, const uint32_t* a,
                                         uint32_t b0, uint32_t b1) {
    asm("mma.sync.aligned.m16n8k8.row.col.f32.tf32.tf32.f32 "
        "{%0,%1,%2,%3}, {%4,%5,%6,%7}, {%8,%9}, {%0,%1,%2,%3};"
        : "+f"(c[0]), "+f"(c[1]), "+f"(c[2]), "+f"(c[3])
        : "r"(a[0]), "r"(a[1]), "r"(a[2]), "r"(a[3]), "r"(b0), "r"(b1));
}

// ---------------------------------------------------------------------------
// tf32 GEMM, split-K=2. 128 threads (4 warps, 32x32 warptiles). [R4, proven]
// ---------------------------------------------------------------------------
__global__ void __launch_bounds__(128, 2) gemm_tf32_kernel(
    const float* __restrict__ X, const float* __restrict__ Wt)
{
    extern __shared__ float smem[];

    const int tid  = threadIdx.x;
    const int lane = tid & 31, warp = tid >> 5;
    const int wm = warp >> 1, wn = warp & 1;          // 2x2 warps, 32x32 tiles
    const int nb = blockIdx.x, mb = blockIdx.y, kz = blockIdx.z;

    const float* Ag = X  + (size_t)mb * 64 * KDIM + (size_t)kz * KHALF;
    const float* Bg = Wt + (size_t)nb * 64 * KDIM + (size_t)kz * KHALF;

    const uint32_t sBase = (uint32_t)__cvta_generic_to_shared(smem);
    const uint32_t bOfs  = STAGES * 16384u;           // B region at 48 KB

    float acc[2][4][4];
#pragma unroll
    for (int a1 = 0; a1 < 2; ++a1)
#pragma unroll
        for (int a2 = 0; a2 < 4; ++a2)
#pragma unroll
            for (int a3 = 0; a3 < 4; ++a3) acc[a1][a2][a3] = 0.0f;

    const int j = lane >> 3, r = lane & 7;
    const int cja = (j >> 1);
    const int cjb = (j & 1);
    const uint32_t aRow0 = (uint32_t)((wm * 32 + (j & 1) * 8 + r) * 256);
    const uint32_t aRow1 = aRow0 + 16u * 256u;
    const uint32_t bRow0 = (uint32_t)((wn * 32 + (j >> 1) * 8 + r) * 256);
    const uint32_t bRow1 = bRow0 + 16u * 256u;

#define ISSUE(kt) {                                                            \
        int stg_ = (kt) % STAGES;                                              \
        uint32_t sa_ = sBase + (uint32_t)stg_ * 16384u;                        \
        uint32_t sb_ = sa_ + bOfs;                                             \
        const float* pa_ = Ag + (size_t)(kt) * BK;                             \
        const float* pb_ = Bg + (size_t)(kt) * BK;                             \
        _Pragma("unroll")                                                      \
        for (int i_ = 0; i_ < 8; ++i_) {                                       \
            int id_ = tid + 128 * i_;                                          \
            int row_ = id_ >> 4, c_ = id_ & 15;                                \
            uint32_t off_ = (uint32_t)(row_ * 256 + ((c_ ^ (row_ & 7)) << 4)); \
            cp_async16(sa_ + off_, pa_ + (size_t)row_ * KDIM + c_ * 4);        \
            cp_async16(sb_ + off_, pb_ + (size_t)row_ * KDIM + c_ * 4);        \
        } }

#define COMPUTE(stg) {                                                         \
        uint32_t aB = sBase + (uint32_t)(stg) * 16384u;                        \
        uint32_t bB = aB + bOfs;                                               \
        _Pragma("unroll")                                                      \
        for (int s = 0; s < 8; ++s) {                                          \
            uint32_t av[2][4], bv[2][4];                                       \
            uint32_t ca = (uint32_t)((((2 * s + cja) ^ r)) << 4);              \
            uint32_t cb = (uint32_t)((((2 * s + cjb) ^ r)) << 4);              \
            ldsm_x4(av[0], aB + aRow0 + ca);                                   \
            ldsm_x4(av[1], aB + aRow1 + ca);                                   \
            ldsm_x4(bv[0], bB + bRow0 + cb);                                   \
            ldsm_x4(bv[1], bB + bRow1 + cb);                                   \
            _Pragma("unroll")                                                  \
            for (int q = 0; q < 4; ++q) {                                      \
                av[0][q] = f2tf(av[0][q]); av[1][q] = f2tf(av[1][q]);          \
                bv[0][q] = f2tf(bv[0][q]); bv[1][q] = f2tf(bv[1][q]);          \
            }                                                                  \
            _Pragma("unroll")                                                  \
            for (int mt = 0; mt < 2; ++mt) {                                   \
                mma_tf32(acc[mt][0], av[mt], bv[0][0], bv[0][1]);              \
                mma_tf32(acc[mt][1], av[mt], bv[0][2], bv[0][3]);              \
                mma_tf32(acc[mt][2], av[mt], bv[1][0], bv[1][1]);              \
                mma_tf32(acc[mt][3], av[mt], bv[1][2], bv[1][3]);              \
            }                                                                  \
        } }

    ISSUE(0); asm volatile("cp.async.commit_group;");
    ISSUE(1); asm volatile("cp.async.commit_group;");

    for (int kt = 0; kt < NT2; ++kt) {
        asm volatile("cp.async.wait_group 1;");
        __syncthreads();
        COMPUTE(kt % STAGES);
        if (kt + 2 < NT2) { ISSUE(kt + 2); }
        asm volatile("cp.async.commit_group;");
    }

    float* P = g_part + (size_t)kz * (128 * 4096);
    const int rbase = mb * 64 + wm * 32 + (lane >> 2);
    const int cbase = nb * 64 + wn * 32 + (lane & 3) * 2;
#pragma unroll
    for (int mt = 0; mt < 2; ++mt) {
#pragma unroll
        for (int nt = 0; nt < 4; ++nt) {
            int gn  = cbase + nt * 8;
            int gm0 = rbase + mt * 16;
            float2 o0; o0.x = acc[mt][nt][0]; o0.y = acc[mt][nt][1];
            *reinterpret_cast<float2*>(P + (size_t)gm0 * 4096 + gn) = o0;
            float2 o1; o1.x = acc[mt][nt][2]; o1.y = acc[mt][nt][3];
            *reinterpret_cast<float2*>(P + (size_t)(gm0 + 8) * 4096 + gn) = o1;
        }
    }
#undef ISSUE
#undef COMPUTE
}

// ---------------------------------------------------------------------------
// Wavelet kernel: one block per image, 256 threads. Rank-select quantile
// prune: per lane rank = #(smaller) via independent shfl_xor compares
// (no dependent sorting chain), then ballot locates rank lo2 / lo2+1.
// ---------------------------------------------------------------------------
__global__ void __launch_bounds__(256) wavelet_kernel(
    const float* __restrict__ x, const float* __restrict__ sf)
{
    __shared__ float A[4096];           // 64x64 image / reconstruction
    __shared__ float Wb0[1024];
    __shared__ float Wb1[1024];
    __shared__ float lev[5440];         // 4096 + 1024 + 256 + 64

    const int b      = blockIdx.x;
    const int tid    = threadIdx.x;
    const int warpId = tid >> 5;
    const int lane   = tid & 31;
    const float* xb  = x + (size_t)b * 4096;

    for (int i = tid; i < 4096; i += 256) A[i] = xb[i];
    __syncthreads();

    const int loff[4] = {0, 4096, 5120, 5376};

    float* cur = A;
    float* nxt = Wb0;

    // ------------- forward: DWT + scale + prune -------------
#pragma unroll
    for (int l = 0; l < 4; ++l) {
        const int h = 64 >> l, hh = h >> 1;
        const float s0 = sf[l * 4 + 0], s1 = sf[l * 4 + 1];
        const float s2 = sf[l * 4 + 2], s3 = sf[l * 4 + 3];
        float* L = lev + loff[l];
        const int n = hh * hh;

        for (int idx = tid; idx < n; idx += 256) {
            int i = idx / hh, jj = idx - i * hh;
            float a  = cur[(2 * i)     * h + 2 * jj];
            float bb = cur[(2 * i)     * h + 2 * jj + 1];
            float c  = cur[(2 * i + 1) * h + 2 * jj];
            float d  = cur[(2 * i + 1) * h + 2 * jj + 1];
            float ca = (a + bb + c + d) * 0.5f;
            float ch = (a - bb + c - d) * 0.5f;
            float cv = (a + bb - c - d) * 0.5f;
            float cd = (a - bb - c + d) * 0.5f;
            nxt[idx] = ca;   // raw cA feeds next level
            L[(0 * hh + i) * hh + jj] = ca * s0;
            L[(1 * hh + i) * hh + jj] = ch * s1;
            L[(2 * hh + i) * hh + jj] = cv * s2;
            L[(3 * hh + i) * hh + jj] = cd * s3;
        }
        __syncthreads();

        // prune: per-row 0.4 quantile via parallel rank selection
        {
            const int rpw  = 32 / hh;          // rows packed per warp pass
            const int t    = lane & (hh - 1);  // local index within row group
            const int sub  = lane / hh;        // packed-row index in warp
            const int gb   = lane & ~(hh - 1); // group base lane
            const int lo2  = (int)(0.4f * (float)(hh - 1));
            const float frac = 0.4f * (float)(hh - 1) - (float)lo2;
            const unsigned gmask =
                (hh == 32) ? 0xffffffffu : (((1u << hh) - 1u) << gb);

            for (int base = warpId * rpw; base < 4 * hh; base += 8 * rpw) {
                int row = base + sub;
                float* rp = L + row * hh;
                float orig = rp[t];
                float v = fabsf(orig);
                int rank = 0;
#pragma unroll
                for (int d = 1; d < hh; ++d) {
                    float o = __shfl_xor_sync(0xffffffffu, v, d);
                    int jl  = lane ^ d;
                    rank += (o < v || (o == v && jl < lane)) ? 1 : 0;
                }
                unsigned mlo = __ballot_sync(0xffffffffu, rank == lo2);
                unsigned mhi = __ballot_sync(0xffffffffu, rank == lo2 + 1);
                int srcLo = __ffs(mlo & gmask) - 1;
                int srcHi = __ffs(mhi & gmask) - 1;
                float vlo = __shfl_sync(0xffffffffu, v, srcLo);
                float vhi = __shfl_sync(0xffffffffu, v, srcHi);
                float thr = vlo + frac * (vhi - vlo);
                rp[t] = (v > thr) ? orig : 0.0f;
            }
        }
        __syncthreads();

        float* newcur = nxt;
        nxt = (newcur == Wb0) ? Wb1 : Wb0;
        cur = newcur;
    }

    // ------------- reconstruction -------------
    if (tid < 16) Wb0[tid] = lev[5376 + tid];   // pruned+scaled cA of level 3
    __syncthreads();

    cur = Wb0;
#pragma unroll
    for (int l = 3; l >= 0; --l) {
        const int hh = 32 >> l, h2 = 2 * hh;
        const int n = hh * hh;
        float* L = lev + loff[l];
        float* outb = (l == 0) ? A : ((cur == Wb0) ? Wb1 : Wb0);

        for (int idx = tid; idx < n; idx += 256) {
            int i = idx / hh, jj = idx - i * hh;
            float ca = cur[idx];
            float ch = L[(1 * hh + i) * hh + jj];
            float cv = L[(2 * hh + i) * hh + jj];
            float cd = L[(3 * hh + i) * hh + jj];
            float a  = (ca + ch + cv + cd) * 0.5f;
            float bb = (ca - ch + cv - cd) * 0.5f;
            float c  = (ca + ch - cv - cd) * 0.5f;
            float d  = (ca - ch - cv + cd) * 0.5f;
            outb[(2 * i)     * h2 + 2 * jj]     = a;
            outb[(2 * i)     * h2 + 2 * jj + 1] = bb;
            outb[(2 * i + 1) * h2 + 2 * jj]     = c;
            outb[(2 * i + 1) * h2 + 2 * jj + 1] = d;
        }
        __syncthreads();
        cur = outb;
    }

    float4* wout = reinterpret_cast<float4*>(g_wav + (size_t)b * 4096);
    const float4* Av = reinterpret_cast<const float4*>(A);
    for (int i = tid; i < 1024; i += 256) wout[i] = Av[i];
}

// ---------------------------------------------------------------------------
// Wide reduce: out = p0 + p1 + bias + wavelet. 512 CTAs x 256 thr, 1 float4/thr.
// ---------------------------------------------------------------------------
__global__ void __launch_bounds__(256) reduce_kernel(
    const float* __restrict__ bias, float* __restrict__ out)
{
    const int i = blockIdx.x * 256 + threadIdx.x;   // float4 index, 131072 total
    const float4 p0 = reinterpret_cast<const float4*>(g_part)[i];
    const float4 p1 = reinterpret_cast<const float4*>(g_part + 128 * 4096)[i];
    const float4 wv = reinterpret_cast<const float4*>(g_wav)[i];
    const float4 bb = reinterpret_cast<const float4*>(bias)[i & 1023];
    float4 o;
    o.x = p0.x + p1.x + bb.x + wv.x;
    o.y = p0.y + p1.y + bb.y + wv.y;
    o.z = p0.z + p1.z + bb.z + wv.z;
    o.w = p0.w + p1.w + bb.w + wv.w;
    reinterpret_cast<float4*>(out)[i] = o;
}

// ---------------------------------------------------------------------------
// Launch
// ---------------------------------------------------------------------------
extern "C" void kernel_launch(void* const* d_in, const int* in_sizes, int n_in,
                              void* d_out, int out_size)
{
    const float* x    = (const float*)d_in[0];   // [128, 4096]
    const float* Wt   = (const float*)d_in[1];   // [4096, 4096]
    const float* bias = (const float*)d_in[2];   // [4096]
    const float* sf   = (const float*)d_in[3];   // [4, 4]
    float* out = (float*)d_out;                  // [128, 4096]

    (void)in_sizes; (void)n_in; (void)out_size;

    const int smemBytes = STAGES * 16384 * 2;    // 96 KB
    cudaFuncSetAttribute(gemm_tf32_kernel,
                         cudaFuncAttributeMaxDynamicSharedMemorySize, smemBytes);

    wavelet_kernel<<<128, 256>>>(x, sf);
    dim3 grid(64, 2, SK);
    gemm_tf32_kernel<<<grid, 128, smemBytes>>>(x, Wt);
    reduce_kernel<<<512, 256>>>(bias, out);
}

// round 6
// speedup vs baseline: 1.1570x; 1.1570x over previous
#include <cuda_runtime.h>
#include <cstdint>

// ============================================================================
// WaveletKAN: out[128,4096] = x @ W^T + wavelet(x) + bias
//   K1 (fat): bid 0..127   -> wavelet blocks (DWT4 + register rank-select
//                             prune + IDWT) -> g_wav
//             bid 128..383 -> tf32 mma.sync GEMM blocks, split-K=2,
//                             BM64 BN64 BK64, 2-stage cp.async -> g_part
//             3 CTAs/SM (64KB smem) => 384 CTAs in ONE wave: wavelet latency
//             is hidden under the GEMM.
//   K2: wide reduce: out = p0 + p1 + bias + g_wav
// ============================================================================

#define KDIM   4096
#define SK     2
#define KHALF  (KDIM / SK)        // 2048
#define BK     64
#define NT2    (KHALF / BK)       // 32

__device__ float g_part[SK * 128 * 4096];   // split-K partials (4 MB)
__device__ float g_wav[128 * 4096];         // wavelet output (2 MB)

// ---------------------------------------------------------------------------
// GEMM helpers
// ---------------------------------------------------------------------------
__device__ __forceinline__ void cp_async16(uint32_t dst, const void* src) {
    asm volatile("cp.async.cg.shared.global [%0], [%1], 16;\n" :: "r"(dst), "l"(src));
}
__device__ __forceinline__ void ldsm_x4(uint32_t* d, uint32_t addr) {
    asm volatile("ldmatrix.sync.aligned.m8n8.x4.shared.b16 {%0,%1,%2,%3}, [%4];"
        : "=r"(d[0]), "=r"(d[1]), "=r"(d[2]), "=r"(d[3]) : "r"(addr));
}
__device__ __forceinline__ uint32_t f2tf(uint32_t v) {
    uint32_t r;
    asm("cvt.rna.tf32.f32 %0, %1;" : "=r"(r) : "f"(__uint_as_float(v)));
    return r;
}
__device__ __forceinline__ void mma_tf32(float* c, const uint32_t* a,
                                         uint32_t b0, uint32_t b1) {
    asm("mma.sync.aligned.m16n8k8.row.col.f32.tf32.tf32.f32 "
        "{%0,%1,%2,%3}, {%4,%5,%6,%7}, {%8,%9}, {%0,%1,%2,%3};"
        : "+f"(c[0]), "+f"(c[1]), "+f"(c[2]), "+f"(c[3])
        : "r"(a[0]), "r"(a[1]), "r"(a[2]), "r"(a[3]), "r"(b0), "r"(b1));
}

// ---------------------------------------------------------------------------
// Register rank-select prune: 0.4-quantile of |val| over the HH-lane group
// this lane belongs to; zero values <= interpolated threshold.
// All 32 lanes of the warp MUST call this (warp-collective).
// ---------------------------------------------------------------------------
template<int HH>
__device__ __forceinline__ float prune_coef(float val) {
    const int lane = (int)(threadIdx.x & 31);
    const int t  = lane & (HH - 1);
    const int gb = lane & ~(HH - 1);
    const unsigned gmask = (HH == 32) ? 0xffffffffu : (((1u << HH) - 1u) << gb);
    const float pos  = 0.4f * (float)(HH - 1);
    const int   lo2  = (int)pos;
    const float frac = pos - (float)lo2;

    float v = fabsf(val);
    int rank = 0;
#pragma unroll
    for (int d = 1; d < HH; ++d) {
        float o = __shfl_xor_sync(0xffffffffu, v, d);
        int to  = t ^ d;
        rank += (o < v || (o == v && to < t)) ? 1 : 0;
    }
    unsigned mlo = __ballot_sync(0xffffffffu, rank == lo2)     & gmask;
    unsigned mhi = __ballot_sync(0xffffffffu, rank == lo2 + 1) & gmask;
    float vlo = __shfl_sync(0xffffffffu, v, __ffs(mlo) - 1);
    float vhi = __shfl_sync(0xffffffffu, v, __ffs(mhi) - 1);
    float thr = vlo + frac * (vhi - vlo);
    return (v > thr) ? val : 0.0f;
}

// One forward DWT level: reads cur (HxH), writes raw cA to nxt (HHxHH) and
// pruned, scaled subbands to Lbuf. 4 warps. One __syncthreads by the caller.
template<int L>
__device__ __forceinline__ void dwt_level(const float* __restrict__ cur,
                                          float* __restrict__ nxt,
                                          float* __restrict__ Lbuf,
                                          const float* __restrict__ sf,
                                          int warp, int lane)
{
    constexpr int H   = 64 >> L;
    constexpr int HH  = H >> 1;
    constexpr int RPW = 32 / HH;          // rows packed per warp pass
    const int t   = lane & (HH - 1);
    const int sub = lane >> (5 - L);      // lane / HH
    const float s0 = sf[L * 4 + 0], s1 = sf[L * 4 + 1];
    const float s2 = sf[L * 4 + 2], s3 = sf[L * 4 + 3];

    for (int ibase = warp * RPW; ibase < HH; ibase += 4 * RPW) {
        int i = ibase + sub;              // may exceed HH-1 when L==3; guarded
        int il = i & (HH - 1);            // clamped for safe (junk) loads
        const float* r0 = cur + (2 * il)     * H + 2 * t;
        const float* r1 = cur + (2 * il + 1) * H + 2 * t;
        float a = r0[0], b = r0[1], c = r1[0], d = r1[1];
        float ca = (a + b + c + d) * 0.5f;
        float ch = (a - b + c - d) * 0.5f;
        float cv = (a + b - c - d) * 0.5f;
        float cd = (a - b - c + d) * 0.5f;

        // warp-collective prunes: ALL lanes participate
        float pch = prune_coef<HH>(ch * s1);
        float pcv = prune_coef<HH>(cv * s2);
        float pcd = prune_coef<HH>(cd * s3);
        float pca = 0.0f;
        if (L == 3) pca = prune_coef<HH>(ca * s0);

        if (i < HH) {
            nxt[i * HH + t] = ca;                      // raw cA feeds next level
            if (L == 3) Lbuf[(0 * HH + i) * HH + t] = pca;
            Lbuf[(1 * HH + i) * HH + t] = pch;
            Lbuf[(2 * HH + i) * HH + t] = pcv;
            Lbuf[(3 * HH + i) * HH + t] = pcd;
        }
    }
}

// ---------------------------------------------------------------------------
// Fat kernel: bid<128 -> wavelet, else GEMM. 128 threads, 3 CTAs/SM, 64KB smem.
// ---------------------------------------------------------------------------
__global__ void __launch_bounds__(128, 3) fat_kernel(
    const float* __restrict__ X, const float* __restrict__ Wt,
    const float* __restrict__ sf)
{
    extern __shared__ float smem[];
    const int bid = blockIdx.x;
    const int tid = threadIdx.x;
    const int lane = tid & 31, warp = tid >> 5;

    if (bid < 128) {
        // ================= WAVELET branch =================
        float* A   = smem;                 // 4096 floats (64x64)
        float* Wb0 = smem + 4096;          // 1024
        float* Wb1 = smem + 5120;          // 1024
        float* lev = smem + 6144;          // 5440
        const int loff[4] = {0, 4096, 5120, 5376};

        const int b = bid;
        const float4* xb = reinterpret_cast<const float4*>(X + (size_t)b * 4096);
        float4* Af = reinterpret_cast<float4*>(A);
        for (int i = tid; i < 1024; i += 128) Af[i] = xb[i];
        __syncthreads();

        // forward: DWT + register prune (one barrier per level)
        dwt_level<0>(A,   Wb0, lev + loff[0], sf, warp, lane); __syncthreads();
        dwt_level<1>(Wb0, Wb1, lev + loff[1], sf, warp, lane); __syncthreads();
        dwt_level<2>(Wb1, Wb0, lev + loff[2], sf, warp, lane); __syncthreads();
        dwt_level<3>(Wb0, Wb1, lev + loff[3], sf, warp, lane); __syncthreads();

        // reconstruction: start from pruned+scaled cA of level 3
        if (tid < 16) Wb0[tid] = lev[5376 + tid];
        __syncthreads();

        float* cur = Wb0;
#pragma unroll
        for (int l = 3; l >= 0; --l) {
            const int hh = 32 >> l, h2 = 2 * hh;
            const int n = hh * hh;
            float* L = lev + loff[l];
            float* outb = (l == 0) ? A : ((cur == Wb0) ? Wb1 : Wb0);

            for (int idx = tid; idx < n; idx += 128) {
                int i = idx / hh, jj = idx - i * hh;
                float ca = cur[idx];
                float ch = L[(1 * hh + i) * hh + jj];
                float cv = L[(2 * hh + i) * hh + jj];
                float cd = L[(3 * hh + i) * hh + jj];
                float a  = (ca + ch + cv + cd) * 0.5f;
                float bb = (ca - ch + cv - cd) * 0.5f;
                float c  = (ca + ch - cv - cd) * 0.5f;
                float d  = (ca - ch - cv + cd) * 0.5f;
                outb[(2 * i)     * h2 + 2 * jj]     = a;
                outb[(2 * i)     * h2 + 2 * jj + 1] = bb;
                outb[(2 * i + 1) * h2 + 2 * jj]     = c;
                outb[(2 * i + 1) * h2 + 2 * jj + 1] = d;
            }
            __syncthreads();
            cur = outb;
        }

        float4* wout = reinterpret_cast<float4*>(g_wav + (size_t)b * 4096);
        for (int i = tid; i < 1024; i += 128) wout[i] = Af[i];
        return;
    }

    // ================= GEMM branch =================
    const int g  = bid - 128;
    const int nb = g & 63, mb = (g >> 6) & 1, kz = g >> 7;
    const int wm = warp >> 1, wn = warp & 1;          // 2x2 warps, 32x32 tiles

    const float* Ag = X  + (size_t)mb * 64 * KDIM + (size_t)kz * KHALF;
    const float* Bg = Wt + (size_t)nb * 64 * KDIM + (size_t)kz * KHALF;

    const uint32_t sBase = (uint32_t)__cvta_generic_to_shared(smem);
    const uint32_t bOfs  = 2u * 16384u;               // B region at 32 KB

    float acc[2][4][4];
#pragma unroll
    for (int a1 = 0; a1 < 2; ++a1)
#pragma unroll
        for (int a2 = 0; a2 < 4; ++a2)
#pragma unroll
            for (int a3 = 0; a3 < 4; ++a3) acc[a1][a2][a3] = 0.0f;

    const int j = lane >> 3, r = lane & 7;
    const int cja = (j >> 1);
    const int cjb = (j & 1);
    const uint32_t aRow0 = (uint32_t)((wm * 32 + (j & 1) * 8 + r) * 256);
    const uint32_t aRow1 = aRow0 + 16u * 256u;
    const uint32_t bRow0 = (uint32_t)((wn * 32 + (j >> 1) * 8 + r) * 256);
    const uint32_t bRow1 = bRow0 + 16u * 256u;

#define ISSUE(kt) {                                                            \
        int stg_ = (kt) & 1;                                                   \
        uint32_t sa_ = sBase + (uint32_t)stg_ * 16384u;                        \
        uint32_t sb_ = sa_ + bOfs;                                             \
        const float* pa_ = Ag + (size_t)(kt) * BK;                             \
        const float* pb_ = Bg + (size_t)(kt) * BK;                             \
        _Pragma("unroll")                                                      \
        for (int i_ = 0; i_ < 8; ++i_) {                                       \
            int id_ = tid + 128 * i_;                                          \
            int row_ = id_ >> 4, c_ = id_ & 15;                                \
            uint32_t off_ = (uint32_t)(row_ * 256 + ((c_ ^ (row_ & 7)) << 4)); \
            cp_async16(sa_ + off_, pa_ + (size_t)row_ * KDIM + c_ * 4);        \
            cp_async16(sb_ + off_, pb_ + (size_t)row_ * KDIM + c_ * 4);        \
        } }

#define COMPUTE(stg) {                                                         \
        uint32_t aB = sBase + (uint32_t)(stg) * 16384u;                        \
        uint32_t bB = aB + bOfs;                                               \
        _Pragma("unroll")                                                      \
        for (int s = 0; s < 8; ++s) {                                          \
            uint32_t av[2][4], bv[2][4];                                       \
            uint32_t ca = (uint32_t)((((2 * s + cja) ^ r)) << 4);              \
            uint32_t cb = (uint32_t)((((2 * s + cjb) ^ r)) << 4);              \
            ldsm_x4(av[0], aB + aRow0 + ca);                                   \
            ldsm_x4(av[1], aB + aRow1 + ca);                                   \
            ldsm_x4(bv[0], bB + bRow0 + cb);                                   \
            ldsm_x4(bv[1], bB + bRow1 + cb);                                   \
            _Pragma("unroll")                                                  \
            for (int q = 0; q < 4; ++q) {                                      \
                av[0][q] = f2tf(av[0][q]); av[1][q] = f2tf(av[1][q]);          \
                bv[0][q] = f2tf(bv[0][q]); bv[1][q] = f2tf(bv[1][q]);          \
            }                                                                  \
            _Pragma("unroll")                                                  \
            for (int mt = 0; mt < 2; ++mt) {                                   \
                mma_tf32(acc[mt][0], av[mt], bv[0][0], bv[0][1]);              \
                mma_tf32(acc[mt][1], av[mt], bv[0][2], bv[0][3]);              \
                mma_tf32(acc[mt][2], av[mt], bv[1][0], bv[1][1]);              \
                mma_tf32(acc[mt][3], av[mt], bv[1][2], bv[1][3]);              \
            }                                                                  \
        } }

    ISSUE(0); asm volatile("cp.async.commit_group;");
    ISSUE(1); asm volatile("cp.async.commit_group;");

    for (int kt = 0; kt < NT2; ++kt) {
        asm volatile("cp.async.wait_group 1;");
        __syncthreads();
        COMPUTE(kt & 1);
        __syncthreads();                   // all reads done before overwrite
        if (kt + 2 < NT2) { ISSUE(kt + 2); }
        asm volatile("cp.async.commit_group;");
    }

    float* P = g_part + (size_t)kz * (128 * 4096);
    const int rbase = mb * 64 + wm * 32 + (lane >> 2);
    const int cbase = nb * 64 + wn * 32 + (lane & 3) * 2;
#pragma unroll
    for (int mt = 0; mt < 2; ++mt) {
#pragma unroll
        for (int nt = 0; nt < 4; ++nt) {
            int gn  = cbase + nt * 8;
            int gm0 = rbase + mt * 16;
            float2 o0; o0.x = acc[mt][nt][0]; o0.y = acc[mt][nt][1];
            *reinterpret_cast<float2*>(P + (size_t)gm0 * 4096 + gn) = o0;
            float2 o1; o1.x = acc[mt][nt][2]; o1.y = acc[mt][nt][3];
            *reinterpret_cast<float2*>(P + (size_t)(gm0 + 8) * 4096 + gn) = o1;
        }
    }
#undef ISSUE
#undef COMPUTE
}

// ---------------------------------------------------------------------------
// Wide reduce: out = p0 + p1 + bias + wavelet. 512 CTAs x 256 thr.
// ---------------------------------------------------------------------------
__global__ void __launch_bounds__(256) reduce_kernel(
    const float* __restrict__ bias, float* __restrict__ out)
{
    const int i = blockIdx.x * 256 + threadIdx.x;   // float4 index, 131072 total
    const float4 p0 = reinterpret_cast<const float4*>(g_part)[i];
    const float4 p1 = reinterpret_cast<const float4*>(g_part + 128 * 4096)[i];
    const float4 wv = reinterpret_cast<const float4*>(g_wav)[i];
    const float4 bb = reinterpret_cast<const float4*>(bias)[i & 1023];
    float4 o;
    o.x = p0.x + p1.x + bb.x + wv.x;
    o.y = p0.y + p1.y + bb.y + wv.y;
    o.z = p0.z + p1.z + bb.z + wv.z;
    o.w = p0.w + p1.w + bb.w + wv.w;
    reinterpret_cast<float4*>(out)[i] = o;
}

// ---------------------------------------------------------------------------
// Launch
// ---------------------------------------------------------------------------
extern "C" void kernel_launch(void* const* d_in, const int* in_sizes, int n_in,
                              void* d_out, int out_size)
{
    const float* x    = (const float*)d_in[0];   // [128, 4096]
    const float* Wt   = (const float*)d_in[1];   // [4096, 4096]
    const float* bias = (const float*)d_in[2];   // [4096]
    const float* sf   = (const float*)d_in[3];   // [4, 4]
    float* out = (float*)d_out;                  // [128, 4096]

    (void)in_sizes; (void)n_in; (void)out_size;

    const int smemBytes = 65536;                 // 64 KB -> 3 CTAs/SM
    cudaFuncSetAttribute(fat_kernel,
                         cudaFuncAttributeMaxDynamicSharedMemorySize, smemBytes);

    fat_kernel<<<384, 128, smemBytes>>>(x, Wt, sf);
    reduce_kernel<<<512, 256>>>(bias, out);
}

// round 7
// speedup vs baseline: 1.4611x; 1.2628x over previous
#include <cuda_runtime.h>
#include <cstdint>

// ============================================================================
// WaveletKAN: out[128,4096] = x @ W^T + wavelet(x) + bias
//   K1 (fat, grid 288, 128 thr, 96KB smem, 2 CTAs/SM => single wave):
//     bid 0..31   -> wavelet CTAs, 4 images each (DWT4 + per-thread register
//                    bitonic-sort quantile prune + IDWT) -> g_wav
//     bid 32..287 -> tf32 mma.sync GEMM (R4-proven: 3-stage cp.async,
//                    BM64 BN64 BK64, split-K=2) -> g_part
//   K2: wide reduce: out = p0 + p1 + bias + g_wav
// ============================================================================

#define KDIM   4096
#define SK     2
#define KHALF  (KDIM / SK)        // 2048
#define BK     64
#define NT2    (KHALF / BK)       // 32
#define STAGES 3

__device__ float g_part[SK * 128 * 4096];   // split-K partials (4 MB)
__device__ float g_wav[128 * 4096];         // wavelet output (2 MB)

// ---------------------------------------------------------------------------
// GEMM helpers
// ---------------------------------------------------------------------------
__device__ __forceinline__ void cp_async16(uint32_t dst, const void* src) {
    asm volatile("cp.async.cg.shared.global [%0], [%1], 16;\n" :: "r"(dst), "l"(src));
}
__device__ __forceinline__ void ldsm_x4(uint32_t* d, uint32_t addr) {
    asm volatile("ldmatrix.sync.aligned.m8n8.x4.shared.b16 {%0,%1,%2,%3}, [%4];"
        : "=r"(d[0]), "=r"(d[1]), "=r"(d[2]), "=r"(d[3]) : "r"(addr));
}
__device__ __forceinline__ uint32_t f2tf(uint32_t v) {
    uint32_t r;
    asm("cvt.rna.tf32.f32 %0, %1;" : "=r"(r) : "f"(__uint_as_float(v)));
    return r;
}
__device__ __forceinline__ void mma_tf32(float* c, const uint32_t* a,
                                         uint32_t b0, uint32_t b1) {
    asm("mma.sync.aligned.m16n8k8.row.col.f32.tf32.tf32.f32 "
        "{%0,%1,%2,%3}, {%4,%5,%6,%7}, {%8,%9}, {%0,%1,%2,%3};"
        : "+f"(c[0]), "+f"(c[1]), "+f"(c[2]), "+f"(c[3])
        : "r"(a[0]), "r"(a[1]), "r"(a[2]), "r"(a[3]), "r"(b0), "r"(b1));
}

// ---------------------------------------------------------------------------
// Per-thread register bitonic sort (ascending). All indices compile-time.
// ---------------------------------------------------------------------------
template<int N>
__device__ __forceinline__ void sortN(float* v) {
#pragma unroll
    for (int k = 2; k <= N; k <<= 1) {
#pragma unroll
        for (int j = k >> 1; j > 0; j >>= 1) {
#pragma unroll
            for (int i = 0; i < N; ++i) {
                int l = i ^ j;
                if (l > i) {
                    float a = v[i], b = v[l];
                    float mn = fminf(a, b), mx = fmaxf(a, b);
                    if ((i & k) == 0) { v[i] = mn; v[l] = mx; }
                    else              { v[i] = mx; v[l] = mn; }
                }
            }
        }
    }
}

// prune one row of N elements in smem: zero values with |v| <= 0.4-quantile(|v|)
template<int N>
__device__ __forceinline__ void prune_row(float* __restrict__ row) {
    float a[N];
#pragma unroll
    for (int i = 0; i < N; ++i) a[i] = fabsf(row[i]);
    sortN<N>(a);
    constexpr float pos = 0.4f * (float)(N - 1);
    constexpr int lo = (int)pos;
    const float frac = pos - (float)lo;
    float thr = a[lo] + frac * (a[lo + 1] - a[lo]);
#pragma unroll
    for (int i = 0; i < N; ++i) {
        float val = row[i];
        row[i] = (fabsf(val) > thr) ? val : 0.0f;
    }
}

// ---------------------------------------------------------------------------
// DWT level: cur (HxH) -> raw cA into nxt (HHxHH), scaled bands into Lb.
// Lb layout: slots 0=cH,1=cV,2=cD (L=3 additionally slot 3 = cA),
// each band HH rows of pitch P=HH+1 (bands contiguous => global row r at r*P).
// ---------------------------------------------------------------------------
template<int LV>
__device__ __forceinline__ void dwt_level(const float* __restrict__ cur,
                                          float* __restrict__ nxt,
                                          float* __restrict__ Lb,
                                          const float* __restrict__ sf, int tid)
{
    constexpr int H = 64 >> LV, HH = H >> 1, P = HH + 1, BS = HH * P;
    const float s0 = sf[LV * 4 + 0], s1 = sf[LV * 4 + 1];
    const float s2 = sf[LV * 4 + 2], s3 = sf[LV * 4 + 3];
    for (int idx = tid; idx < HH * HH; idx += 128) {
        int i = idx / HH, j = idx - i * HH;
        const float* r0 = cur + (2 * i)     * H + 2 * j;
        const float* r1 = cur + (2 * i + 1) * H + 2 * j;
        float a = r0[0], b = r0[1], c = r1[0], d = r1[1];
        float ca = (a + b + c + d) * 0.5f;
        float ch = (a - b + c - d) * 0.5f;
        float cv = (a + b - c - d) * 0.5f;
        float cd = (a - b - c + d) * 0.5f;
        nxt[idx] = ca;                                  // raw cA -> next level
        Lb[0 * BS + i * P + j] = ch * s1;
        Lb[1 * BS + i * P + j] = cv * s2;
        Lb[2 * BS + i * P + j] = cd * s3;
        if (LV == 3) Lb[3 * BS + i * P + j] = ca * s0;  // cA kept only at last level
    }
}

// IDWT level: cur (HHxHH contiguous) + bands (pitched) -> outb (2HHx2HH)
template<int HH>
__device__ __forceinline__ void idwt_level(const float* __restrict__ cur,
                                           const float* __restrict__ Lb,
                                           float* __restrict__ outb, int tid)
{
    constexpr int P = HH + 1, BS = HH * P, H2 = 2 * HH;
    for (int idx = tid; idx < HH * HH; idx += 128) {
        int i = idx / HH, j = idx - i * HH;
        float ca = cur[idx];
        float ch = Lb[0 * BS + i * P + j];
        float cv = Lb[1 * BS + i * P + j];
        float cd = Lb[2 * BS + i * P + j];
        float a  = (ca + ch + cv + cd) * 0.5f;
        float b  = (ca - ch + cv - cd) * 0.5f;
        float c  = (ca + ch - cv - cd) * 0.5f;
        float d  = (ca - ch - cv + cd) * 0.5f;
        outb[(2 * i)     * H2 + 2 * j]     = a;
        outb[(2 * i)     * H2 + 2 * j + 1] = b;
        outb[(2 * i + 1) * H2 + 2 * j]     = c;
        outb[(2 * i + 1) * H2 + 2 * j + 1] = d;
    }
}

// ---------------------------------------------------------------------------
// Fat kernel. bid<32: wavelet (4 images). bid>=32: GEMM (R4 design).
// ---------------------------------------------------------------------------
__global__ void __launch_bounds__(128, 2) fat_kernel(
    const float* __restrict__ X, const float* __restrict__ Wt,
    const float* __restrict__ sf)
{
    extern __shared__ float smem[];
    const int bid = blockIdx.x;
    const int tid = threadIdx.x;
    const int lane = tid & 31, warp = tid >> 5;

    if (bid < 32) {
        // ================= WAVELET branch: 4 images =================
        // smem layout (floats): A 0..4095 | Wb0 4096 | Wb1 5120 |
        //   L0 6144 (3*32*33=3168) | L1 9312 (3*16*17=816) |
        //   L2 10128 (3*8*9=216)   | L3 10344 (4*4*5=80)
        float* A   = smem;
        float* Wb0 = smem + 4096;
        float* Wb1 = smem + 5120;
        float* L0  = smem + 6144;
        float* L1  = smem + 9312;
        float* L2  = smem + 10128;
        float* L3  = smem + 10344;

        for (int im = 0; im < 4; ++im) {
            const int b = bid * 4 + im;
            const float4* xb = reinterpret_cast<const float4*>(X + (size_t)b * 4096);
            float4* Af = reinterpret_cast<float4*>(A);
            for (int i = tid; i < 1024; i += 128) Af[i] = xb[i];
            __syncthreads();

            dwt_level<0>(A,   Wb0, L0, sf, tid); __syncthreads();
            if (tid < 96) prune_row<32>(L0 + tid * 33);
            __syncthreads();
            dwt_level<1>(Wb0, Wb1, L1, sf, tid); __syncthreads();
            if (tid < 48) prune_row<16>(L1 + tid * 17);
            __syncthreads();
            dwt_level<2>(Wb1, Wb0, L2, sf, tid); __syncthreads();
            if (tid < 24) prune_row<8>(L2 + tid * 9);
            __syncthreads();
            dwt_level<3>(Wb0, Wb1, L3, sf, tid); __syncthreads();
            if (tid < 16) prune_row<4>(L3 + tid * 5);
            __syncthreads();

            // reconstruction: seed from pruned scaled cA (L3 slot 3)
            if (tid < 16) {
                int i = tid >> 2, j = tid & 3;
                Wb0[tid] = L3[3 * 20 + i * 5 + j];
            }
            __syncthreads();
            idwt_level<4>(Wb0, L3, Wb1, tid);  __syncthreads();  // 4  -> 8
            idwt_level<8>(Wb1, L2, Wb0, tid);  __syncthreads();  // 8  -> 16
            idwt_level<16>(Wb0, L1, Wb1, tid); __syncthreads();  // 16 -> 32
            idwt_level<32>(Wb1, L0, A, tid);   __syncthreads();  // 32 -> 64

            float4* wout = reinterpret_cast<float4*>(g_wav + (size_t)b * 4096);
            for (int i = tid; i < 1024; i += 128) wout[i] = Af[i];
            __syncthreads();   // protect A before next image's load
        }
        return;
    }

    // ================= GEMM branch (R4-proven) =================
    const int g  = bid - 32;
    const int nb = g & 63, mb = (g >> 6) & 1, kz = g >> 7;
    const int wm = warp >> 1, wn = warp & 1;          // 2x2 warps, 32x32 tiles

    const float* Ag = X  + (size_t)mb * 64 * KDIM + (size_t)kz * KHALF;
    const float* Bg = Wt + (size_t)nb * 64 * KDIM + (size_t)kz * KHALF;

    const uint32_t sBase = (uint32_t)__cvta_generic_to_shared(smem);
    const uint32_t bOfs  = STAGES * 16384u;           // B region at 48 KB

    float acc[2][4][4];
#pragma unroll
    for (int a1 = 0; a1 < 2; ++a1)
#pragma unroll
        for (int a2 = 0; a2 < 4; ++a2)
#pragma unroll
            for (int a3 = 0; a3 < 4; ++a3) acc[a1][a2][a3] = 0.0f;

    const int j = lane >> 3, r = lane & 7;
    const int cja = (j >> 1);
    const int cjb = (j & 1);
    const uint32_t aRow0 = (uint32_t)((wm * 32 + (j & 1) * 8 + r) * 256);
    const uint32_t aRow1 = aRow0 + 16u * 256u;
    const uint32_t bRow0 = (uint32_t)((wn * 32 + (j >> 1) * 8 + r) * 256);
    const uint32_t bRow1 = bRow0 + 16u * 256u;

#define ISSUE(kt) {                                                            \
        int stg_ = (kt) % STAGES;                                              \
        uint32_t sa_ = sBase + (uint32_t)stg_ * 16384u;                        \
        uint32_t sb_ = sa_ + bOfs;                                             \
        const float* pa_ = Ag + (size_t)(kt) * BK;                             \
        const float* pb_ = Bg + (size_t)(kt) * BK;                             \
        _Pragma("unroll")                                                      \
        for (int i_ = 0; i_ < 8; ++i_) {                                       \
            int id_ = tid + 128 * i_;                                          \
            int row_ = id_ >> 4, c_ = id_ & 15;                                \
            uint32_t off_ = (uint32_t)(row_ * 256 + ((c_ ^ (row_ & 7)) << 4)); \
            cp_async16(sa_ + off_, pa_ + (size_t)row_ * KDIM + c_ * 4);        \
            cp_async16(sb_ + off_, pb_ + (size_t)row_ * KDIM + c_ * 4);        \
        } }

#define COMPUTE(stg) {                                                         \
        uint32_t aB = sBase + (uint32_t)(stg) * 16384u;                        \
        uint32_t bB = aB + bOfs;                                               \
        _Pragma("unroll")                                                      \
        for (int s = 0; s < 8; ++s) {                                          \
            uint32_t av[2][4], bv[2][4];                                       \
            uint32_t ca = (uint32_t)((((2 * s + cja) ^ r)) << 4);              \
            uint32_t cb = (uint32_t)((((2 * s + cjb) ^ r)) << 4);              \
            ldsm_x4(av[0], aB + aRow0 + ca);                                   \
            ldsm_x4(av[1], aB + aRow1 + ca);                                   \
            ldsm_x4(bv[0], bB + bRow0 + cb);                                   \
            ldsm_x4(bv[1], bB + bRow1 + cb);                                   \
            _Pragma("unroll")                                                  \
            for (int q = 0; q < 4; ++q) {                                      \
                av[0][q] = f2tf(av[0][q]); av[1][q] = f2tf(av[1][q]);          \
                bv[0][q] = f2tf(bv[0][q]); bv[1][q] = f2tf(bv[1][q]);          \
            }                                                                  \
            _Pragma("unroll")                                                  \
            for (int mt = 0; mt < 2; ++mt) {                                   \
                mma_tf32(acc[mt][0], av[mt], bv[0][0], bv[0][1]);              \
                mma_tf32(acc[mt][1], av[mt], bv[0][2], bv[0][3]);              \
                mma_tf32(acc[mt][2], av[mt], bv[1][0], bv[1][1]);              \
                mma_tf32(acc[mt][3], av[mt], bv[1][2], bv[1][3]);              \
            }                                                                  \
        } }

    ISSUE(0); asm volatile("cp.async.commit_group;");
    ISSUE(1); asm volatile("cp.async.commit_group;");

    for (int kt = 0; kt < NT2; ++kt) {
        asm volatile("cp.async.wait_group 1;");
        __syncthreads();
        COMPUTE(kt % STAGES);
        if (kt + 2 < NT2) { ISSUE(kt + 2); }
        asm volatile("cp.async.commit_group;");
    }

    float* P = g_part + (size_t)kz * (128 * 4096);
    const int rbase = mb * 64 + wm * 32 + (lane >> 2);
    const int cbase = nb * 64 + wn * 32 + (lane & 3) * 2;
#pragma unroll
    for (int mt = 0; mt < 2; ++mt) {
#pragma unroll
        for (int nt = 0; nt < 4; ++nt) {
            int gn  = cbase + nt * 8;
            int gm0 = rbase + mt * 16;
            float2 o0; o0.x = acc[mt][nt][0]; o0.y = acc[mt][nt][1];
            *reinterpret_cast<float2*>(P + (size_t)gm0 * 4096 + gn) = o0;
            float2 o1; o1.x = acc[mt][nt][2]; o1.y = acc[mt][nt][3];
            *reinterpret_cast<float2*>(P + (size_t)(gm0 + 8) * 4096 + gn) = o1;
        }
    }
#undef ISSUE
#undef COMPUTE
}

// ---------------------------------------------------------------------------
// Wide reduce: out = p0 + p1 + bias + wavelet. 256 CTAs x 256 thr x 2 float4.
// ---------------------------------------------------------------------------
__global__ void __launch_bounds__(256) reduce_kernel(
    const float* __restrict__ bias, float* __restrict__ out)
{
    const int base = blockIdx.x * 256 + threadIdx.x;
#pragma unroll
    for (int u = 0; u < 2; ++u) {
        const int i = base + u * 65536;             // float4 index, 131072 total
        const float4 p0 = reinterpret_cast<const float4*>(g_part)[i];
        const float4 p1 = reinterpret_cast<const float4*>(g_part + 128 * 4096)[i];
        const float4 wv = reinterpret_cast<const float4*>(g_wav)[i];
        const float4 bb = reinterpret_cast<const float4*>(bias)[i & 1023];
        float4 o;
        o.x = p0.x + p1.x + bb.x + wv.x;
        o.y = p0.y + p1.y + bb.y + wv.y;
        o.z = p0.z + p1.z + bb.z + wv.z;
        o.w = p0.w + p1.w + bb.w + wv.w;
        reinterpret_cast<float4*>(out)[i] = o;
    }
}

// ---------------------------------------------------------------------------
// Launch
// ---------------------------------------------------------------------------
extern "C" void kernel_launch(void* const* d_in, const int* in_sizes, int n_in,
                              void* d_out, int out_size)
{
    const float* x    = (const float*)d_in[0];   // [128, 4096]
    const float* Wt   = (const float*)d_in[1];   // [4096, 4096]
    const float* bias = (const float*)d_in[2];   // [4096]
    const float* sf   = (const float*)d_in[3];   // [4, 4]
    float* out = (float*)d_out;                  // [128, 4096]

    (void)in_sizes; (void)n_in; (void)out_size;

    const int smemBytes = STAGES * 16384 * 2;    // 96 KB -> 2 CTAs/SM
    cudaFuncSetAttribute(fat_kernel,
                         cudaFuncAttributeMaxDynamicSharedMemorySize, smemBytes);

    fat_kernel<<<288, 128, smemBytes>>>(x, Wt, sf);
    reduce_kernel<<<256, 256>>>(bias, out);
}